// round 13
// baseline (speedup 1.0000x reference)
#include <cuda_runtime.h>
#include <math.h>

#define NN 256
#define TT 1000
#define NO_ 10
#define NS_ 10
#define DD 20      // NO_ + NS_
#define HH 64
#define GG 192     // 3*HH

typedef unsigned long long ull;

// Scratch (no allocations allowed): hidden states
__device__ float g_hs[(size_t)NN * TT * HH];   // 65.5 MB
__device__ double g_acc;
__device__ unsigned int g_done;

// ---- packed f32x2 helpers (Blackwell sm_103a) ------------------------------
__device__ __forceinline__ ull pack2(float lo, float hi) {
    ull r; asm("mov.b64 %0,{%1,%2};" : "=l"(r) : "f"(lo), "f"(hi)); return r;
}
__device__ __forceinline__ float2 unpack2(ull v) {
    float lo, hi; asm("mov.b64 {%0,%1},%2;" : "=f"(lo), "=f"(hi) : "l"(v));
    return make_float2(lo, hi);
}
__device__ __forceinline__ ull fma2(ull a, ull b, ull c) {
    ull d; asm("fma.rn.f32x2 %0,%1,%2,%3;" : "=l"(d) : "l"(a), "l"(b), "l"(c)); return d;
}
__device__ __forceinline__ ull add2(ull a, ull b) {
    ull d; asm("add.rn.f32x2 %0,%1,%2;" : "=l"(d) : "l"(a), "l"(b)); return d;
}
__device__ __forceinline__ float tanh_fast(float x) {
    float y; asm("tanh.approx.f32 %0,%1;" : "=f"(y) : "f"(x)); return y;
}
__device__ __forceinline__ float sigmoid_fast(float x) {
    return fmaf(0.5f, tanh_fast(0.5f * x), 0.5f);
}

#define BAR_SYNC_1()   asm volatile("bar.sync 1, 192;" ::: "memory")
#define BAR_ARRIVE_1() asm volatile("bar.arrive 1, 192;" ::: "memory")

// ---------------------------------------------------------------------------
// GRU scan: 128 blocks x 256 threads, TWO samples per block, exactly ONE
// block per SM (no 2-vs-1 block imbalance across SMs, R10's limiter).
//   threads 0..191  (proj): ONE Wh gate column each (32 ull, shared across
//     both samples); per step: dot products for sample 0 AND sample 1
//     (64 fma2, 8 independent chains). Threads 0..127 additionally run the
//     gate math for (sample = k/64, unit = k%64) -> MUFU spread over all
//     4 SMSPs (warps 0..3).
//   threads 192..255 (producers): THREE Wi columns each (30 ull, shared
//     across samples); compute xp(t+1) for both samples into a depth-2
//     shared ring; producers 0..39 stream x from DRAM (2-step prefetch).
//   Unified ull w[32] register file for both roles (R8 spill fix).
//   Barriers per step: one __syncthreads + split named barrier -> per
//   SAMPLE-step the barrier cost is halved vs R10.
// ---------------------------------------------------------------------------
__global__ void __launch_bounds__(256, 1) gru_scan_kernel(
    const float* __restrict__ Yi, const float* __restrict__ Xh,
    const float* __restrict__ Wi, const float* __restrict__ Wh,
    const float* __restrict__ bi, const float* __restrict__ bh)
{
    __shared__ __align__(16) float sh_h[2][2][HH];   // [slot][sample][unit]
    __shared__ __align__(16) float sh_x[2][2][DD];   // raw input ring
    __shared__ __align__(16) float sh_xp[2][2][GG];  // input-projection ring
    __shared__ float sh_g[2][GG];                    // xp + hproj pre-acts
    __shared__ float sh_hn[2][HH];                   // hproj only, n-gate cols

    const int tid = threadIdx.x;
    const int n0 = blockIdx.x * 2;
    if (blockIdx.x == 0 && tid == 0) { g_acc = 0.0; g_done = 0u; }

    const bool proj = (tid < GG);
    const int k = tid;          // proj column id (valid when proj)
    const int p = tid - GG;     // producer id 0..63 (valid when !proj)

    // ---- unified weight register file (64 regs for BOTH roles) ------------
    ull w[32];
    float b0 = 0.f, b1 = 0.f, b2 = 0.f;
    float hprev = 0.0f;         // gate threads only (k < 128)
    if (proj) {
#pragma unroll
        for (int q = 0; q < HH / 2; q++)
            w[q] = pack2(Wh[(2 * q) * GG + k], Wh[(2 * q + 1) * GG + k]);
        b0 = bh[k];
    } else {
#pragma unroll
        for (int q = 0; q < DD / 2; q++) {
            w[q]      = pack2(Wi[(2 * q) * GG + p],          Wi[(2 * q + 1) * GG + p]);
            w[10 + q] = pack2(Wi[(2 * q) * GG + HH + p],     Wi[(2 * q + 1) * GG + HH + p]);
            w[20 + q] = pack2(Wi[(2 * q) * GG + 2 * HH + p], Wi[(2 * q + 1) * GG + 2 * HH + p]);
        }
        w[30] = 0ull; w[31] = 0ull;
        b0 = bi[p]; b1 = bi[HH + p]; b2 = bi[2 * HH + p];
    }
    if (tid < 2 * HH) sh_h[0][tid >> 6][tid & 63] = 0.0f;

    // x loaders: producers 0..39 own one (sample, feature) slot each
    const float* src = 0;
    float xa = 0.0f, xb = 0.0f;
    if (!proj && p < 2 * DD) {
        const int s = p / DD, j = p - s * DD;
        const int n = n0 + s;
        src = (j < NO_) ? (Yi + (size_t)n * TT * NO_ + j)
                        : (Xh + (size_t)n * TT * NS_ + (j - NO_));
        sh_x[0][s][j] = src[0];              // x(0)
        sh_x[1][s][j] = src[NS_];            // x(1)   (stride NO_==NS_==10)
        xa = src[2 * NS_];                   // x(2)
        xb = src[3 * NS_];                   // x(3)
    }
    __syncthreads();

    // producers: xp(0) for both samples into ring slot 0
    if (!proj) {
#pragma unroll
        for (int s = 0; s < 2; s++) {
            const ull* x2 = (const ull*)sh_x[0][s];
            ull cr = pack2(b0, 0.0f), cz = pack2(b1, 0.0f), cn = pack2(b2, 0.0f);
#pragma unroll
            for (int q = 0; q < DD / 2; q++) {
                cr = fma2(x2[q], w[q],      cr);
                cz = fma2(x2[q], w[10 + q], cz);
                cn = fma2(x2[q], w[20 + q], cn);
            }
            float2 f;
            f = unpack2(cr); sh_xp[0][s][p]          = f.x + f.y;
            f = unpack2(cz); sh_xp[0][s][HH + p]     = f.x + f.y;
            f = unpack2(cn); sh_xp[0][s][2 * HH + p] = f.x + f.y;
        }
    }

    float* hs0 = g_hs + (size_t)n0 * TT * HH;
    float* hs1 = g_hs + (size_t)(n0 + 1) * TT * HH;

    for (int t = 0; t < TT; t++) {
        const int slot = t & 1;
        __syncthreads();   // sh_h[slot], sh_xp[slot], sh_x(t+1) staged

        if (proj) {
            // ---- h-projections for column k, BOTH samples (64 fma2) ----
            const ulonglong2* h4a = (const ulonglong2*)sh_h[slot][0];
            const ulonglong2* h4b = (const ulonglong2*)sh_h[slot][1];
            ull a0 = pack2(b0, 0.0f), a1 = 0ull, a2 = 0ull, a3 = 0ull;
            ull c0 = pack2(b0, 0.0f), c1 = 0ull, c2 = 0ull, c3 = 0ull;
#pragma unroll
            for (int q = 0; q < HH / 4; q += 2) {
                const ulonglong2 ha0 = h4a[q], ha1 = h4a[q + 1];
                const ulonglong2 hb0 = h4b[q], hb1 = h4b[q + 1];
                a0 = fma2(ha0.x, w[2 * q],     a0);
                a1 = fma2(ha0.y, w[2 * q + 1], a1);
                a2 = fma2(ha1.x, w[2 * q + 2], a2);
                a3 = fma2(ha1.y, w[2 * q + 3], a3);
                c0 = fma2(hb0.x, w[2 * q],     c0);
                c1 = fma2(hb0.y, w[2 * q + 1], c1);
                c2 = fma2(hb1.x, w[2 * q + 2], c2);
                c3 = fma2(hb1.y, w[2 * q + 3], c3);
            }
            const float2 fa = unpack2(add2(add2(a0, a1), add2(a2, a3)));
            const float2 fb = unpack2(add2(add2(c0, c1), add2(c2, c3)));
            const float ah0 = fa.x + fa.y;            // h0@Wh_col + bh
            const float ah1 = fb.x + fb.y;            // h1@Wh_col + bh

            sh_g[0][k] = sh_xp[slot][0][k] + ah0;
            sh_g[1][k] = sh_xp[slot][1][k] + ah1;
            if (k >= 2 * HH) {
                sh_hn[0][k - 2 * HH] = ah0;
                sh_hn[1][k - 2 * HH] = ah1;
            }

            if (k < 2 * HH) {
                BAR_SYNC_1();
                const int s = k >> 6, u = k & 63;
                const float r  = sigmoid_fast(sh_g[s][u]);
                const float z  = sigmoid_fast(sh_g[s][HH + u]);
                const float hn = sh_hn[s][u];
                // xn + r*hn = (xn + hn) + (r-1)*hn
                const float nn = tanh_fast(fmaf(r - 1.0f, hn, sh_g[s][2 * HH + u]));
                const float hnew = fmaf(z, hprev - nn, nn);   // (1-z)n + z h
                hprev = hnew;
                sh_h[slot ^ 1][s][u] = hnew;
                (s ? hs1 : hs0)[(size_t)t * HH + u] = hnew;
            } else {
                BAR_ARRIVE_1();
            }
        } else {
            // ---- produce xp(t+1), both samples, into the other slot ----
            if (t + 1 < TT) {
#pragma unroll
                for (int s = 0; s < 2; s++) {
                    const ull* x2 = (const ull*)sh_x[slot ^ 1][s];
                    ull cr = pack2(b0, 0.0f), cz = pack2(b1, 0.0f), cn = pack2(b2, 0.0f);
#pragma unroll
                    for (int q = 0; q < DD / 2; q++) {
                        cr = fma2(x2[q], w[q],      cr);
                        cz = fma2(x2[q], w[10 + q], cz);
                        cn = fma2(x2[q], w[20 + q], cn);
                    }
                    float2 f;
                    f = unpack2(cr); sh_xp[slot ^ 1][s][p]          = f.x + f.y;
                    f = unpack2(cz); sh_xp[slot ^ 1][s][HH + p]     = f.x + f.y;
                    f = unpack2(cn); sh_xp[slot ^ 1][s][2 * HH + p] = f.x + f.y;
                }
            }
            if (p < 2 * DD) {
                const int s = p / DD, j = p - s * DD;
                if (t + 2 < TT) sh_x[slot][s][j] = xa;     // stage x(t+2)
                xa = xb;
                if (t + 4 < TT) xb = src[(size_t)(t + 4) * NS_];
            }
        }
    }
}

// ---------------------------------------------------------------------------
// Likelihood: one thread per (n,t), 128-thread blocks. Heads computed in two
// staged passes (vr then mu) to cut peak register pressure; packed Cholesky.
// Last block writes the final scalar.
// ---------------------------------------------------------------------------
__global__ void __launch_bounds__(128) lik_kernel(
    const float* __restrict__ Yi, const float* __restrict__ Cw,
    const float* __restrict__ Hm, const float* __restrict__ mu_w,
    const float* __restrict__ W_mu, const float* __restrict__ b_mu,
    const float* __restrict__ W_var, const float* __restrict__ b_var,
    float* __restrict__ out)
{
    __shared__ ull sWm2[(HH / 2) * NS_];
    __shared__ ull sWv2[(HH / 2) * NS_];
    __shared__ float sH[NO_ * NS_], sbm[NS_], sbv[NS_], smw[NO_];
    __shared__ double wsum[4];

    const int tid = threadIdx.x;
    for (int i = tid; i < (HH / 2) * NS_; i += 128) {
        const int p = i / NS_, j = i - p * NS_;
        sWm2[i] = pack2(W_mu[(2 * p) * NS_ + j],  W_mu[(2 * p + 1) * NS_ + j]);
        sWv2[i] = pack2(W_var[(2 * p) * NS_ + j], W_var[(2 * p + 1) * NS_ + j]);
    }
    if (tid < NO_ * NS_) sH[tid] = Hm[tid];
    if (tid < NS_) { sbm[tid] = b_mu[tid]; sbv[tid] = b_var[tid]; }
    if (tid < NO_) smw[tid] = mu_w[tid];
    __syncthreads();

    const int idx = blockIdx.x * 128 + tid;      // grid exact: NN*TT/128
    const int n = idx / TT;
    const ulonglong2* h4 = (const ulonglong2*)(g_hs + (size_t)idx * HH);

    // ---- pass 1: vr head -> var (softplus) ----
    float var[NS_];
    {
        ull vr2[NS_];
#pragma unroll
        for (int j = 0; j < NS_; j++) vr2[j] = 0ull;
#pragma unroll
        for (int q = 0; q < HH / 4; q++) {
            const ulonglong2 hv = h4[q];
            const int p0 = 2 * q;
#pragma unroll
            for (int j = 0; j < NS_; j++) vr2[j] = fma2(hv.x, sWv2[p0 * NS_ + j], vr2[j]);
#pragma unroll
            for (int j = 0; j < NS_; j++) vr2[j] = fma2(hv.y, sWv2[(p0 + 1) * NS_ + j], vr2[j]);
        }
#pragma unroll
        for (int j = 0; j < NS_; j++) {
            const float2 v = unpack2(vr2[j]);
            const float x = sbv[j] + v.x + v.y;
            var[j] = (x > 15.0f) ? x : __logf(1.0f + __expf(x));
        }
    }

    // ---- pass 2: mu head -> residual e ----
    float e[NO_];
    {
        ull mu2[NS_];
#pragma unroll
        for (int j = 0; j < NS_; j++) mu2[j] = 0ull;
#pragma unroll
        for (int q = 0; q < HH / 4; q++) {
            const ulonglong2 hv = h4[q];
            const int p0 = 2 * q;
#pragma unroll
            for (int j = 0; j < NS_; j++) mu2[j] = fma2(hv.x, sWm2[p0 * NS_ + j], mu2[j]);
#pragma unroll
            for (int j = 0; j < NS_; j++) mu2[j] = fma2(hv.y, sWm2[(p0 + 1) * NS_ + j], mu2[j]);
        }
        float mu[NS_];
#pragma unroll
        for (int j = 0; j < NS_; j++) {
            const float2 m = unpack2(mu2[j]);
            mu[j] = sbm[j] + m.x + m.y;
        }
#pragma unroll
        for (int i = 0; i < NO_; i++) {
            float m = smw[i];
#pragma unroll
            for (int j = 0; j < NS_; j++) m = fmaf(sH[i * NS_ + j], mu[j], m);
            e[i] = Yi[(size_t)idx * NO_ + i] - m;
        }
    }

    // A = H diag(var) H^T + Cw, packed lower triangle
    float A[NO_ * (NO_ + 1) / 2];
    const float* cw = Cw + (size_t)n * NO_ * NO_;
#pragma unroll
    for (int i = 0; i < NO_; i++)
#pragma unroll
        for (int kk = 0; kk <= i; kk++)
            A[i * (i + 1) / 2 + kk] = cw[i * NO_ + kk];
#pragma unroll
    for (int j = 0; j < NS_; j++) {
        const float vj = var[j];
        float hj[NO_];
#pragma unroll
        for (int i = 0; i < NO_; i++) hj[i] = sH[i * NS_ + j];
#pragma unroll
        for (int i = 0; i < NO_; i++) {
            const float hv = hj[i] * vj;
#pragma unroll
            for (int kk = 0; kk <= i; kk++)
                A[i * (i + 1) / 2 + kk] = fmaf(hv, hj[kk], A[i * (i + 1) / 2 + kk]);
        }
    }

    // in-place packed Cholesky; logdet = sum log(s_i) since Lii^2 = s_i
    float rdi[NO_];
    float logdet = 0.0f;
#pragma unroll
    for (int i = 0; i < NO_; i++) {
#pragma unroll
        for (int kk = 0; kk < i; kk++) {
            float s = A[i * (i + 1) / 2 + kk];
#pragma unroll
            for (int j2 = 0; j2 < NO_; j2++)
                if (j2 < kk)
                    s -= A[i * (i + 1) / 2 + j2] * A[kk * (kk + 1) / 2 + j2];
            A[i * (i + 1) / 2 + kk] = s * rdi[kk];
        }
        float s = A[i * (i + 1) / 2 + i];
#pragma unroll
        for (int j2 = 0; j2 < NO_; j2++)
            if (j2 < i) {
                const float l = A[i * (i + 1) / 2 + j2];
                s -= l * l;
            }
        rdi[i] = rsqrtf(s);
        logdet += __logf(s);
    }

    // forward solve z = L^{-1} e ; quad = |z|^2
    float quad = 0.0f;
    float zv[NO_];
#pragma unroll
    for (int i = 0; i < NO_; i++) {
        float s = e[i];
#pragma unroll
        for (int j2 = 0; j2 < NO_; j2++)
            if (j2 < i) s -= A[i * (i + 1) / 2 + j2] * zv[j2];
        zv[i] = s * rdi[i];
        quad = fmaf(zv[i], zv[i], quad);
    }

    double local = (double)(logdet + quad);

    // block reduction -> one atomicAdd; last block finalizes
    for (int off = 16; off > 0; off >>= 1)
        local += __shfl_down_sync(0xffffffffu, local, off);
    if ((tid & 31) == 0) wsum[tid >> 5] = local;
    __syncthreads();
    if (tid == 0) {
        double s = wsum[0] + wsum[1] + wsum[2] + wsum[3];
        atomicAdd(&g_acc, s);
        __threadfence();
        const unsigned int d = atomicAdd(&g_done, 1u);
        if (d == gridDim.x - 1) {
            __threadfence();
            const double LOG2PI = 1.8378770664093453;
            const double acc = *((volatile double*)&g_acc);
            out[0] = (float)(-0.5 * LOG2PI - 0.5 * acc / ((double)NN * TT * NO_));
        }
    }
}

extern "C" void kernel_launch(void* const* d_in, const int* in_sizes, int n_in,
                              void* d_out, int out_size)
{
    const float* Yi    = (const float*)d_in[0];
    const float* Xh    = (const float*)d_in[1];
    const float* Cw    = (const float*)d_in[2];
    const float* Hm    = (const float*)d_in[3];
    const float* mu_w  = (const float*)d_in[4];
    const float* Wi    = (const float*)d_in[5];
    const float* Wh    = (const float*)d_in[6];
    const float* bi    = (const float*)d_in[7];
    const float* bh    = (const float*)d_in[8];
    const float* W_mu  = (const float*)d_in[9];
    const float* b_mu  = (const float*)d_in[10];
    const float* W_var = (const float*)d_in[11];
    const float* b_var = (const float*)d_in[12];
    float* out = (float*)d_out;

    gru_scan_kernel<<<NN / 2, 256>>>(Yi, Xh, Wi, Wh, bi, bh);
    lik_kernel<<<NN * TT / 128, 128>>>(Yi, Cw, Hm, mu_w, W_mu, b_mu, W_var, b_var, out);
}